// round 16
// baseline (speedup 1.0000x reference)
#include <cuda_runtime.h>
#include <cuda_fp16.h>
#include <cstdint>

#define BB      4
#define CINC    64
#define COUTC   64
#define KNB     16
#define NN      32768
#define PTS     128       // points per tile (= GEMM M)
#define VHW     132       // V row stride in WORDS (264 halves): conflict-free
#define WHW     132       // W4 row stride in WORDS ([o][k] fp16)
#define THREADS 1024
#define GRIDM   148       // persistent CTAs (1/SM)
#define NTILES  (BB * (NN / PTS))   // 1024

// ---- scratch (no allocations allowed) ----
__device__ __half g_featH[(size_t)BB * NN * CINC];   // [b][n][c] fp16
__device__ float4 g_posT [(size_t)BB * NN];          // [b][n] xyz_
__device__ uint4  g_dp2  [(size_t)BB * NN * 8];      // [b][n][kpair]: packed

__device__ __forceinline__ uint64_t pack2(float x, float y) {
    uint64_t r;
    asm("mov.b64 %0, {%1, %2};" : "=l"(r) : "f"(x), "f"(y));
    return r;
}
__device__ __forceinline__ void unpack2(float& x, float& y, uint64_t v) {
    asm("mov.b64 {%0, %1}, %2;" : "=f"(x), "=f"(y) : "l"(v));
}
__device__ __forceinline__ void fma2(uint64_t& d, uint64_t a, uint64_t b) {
    asm("fma.rn.f32x2 %0, %1, %2, %0;" : "+l"(d) : "l"(a), "l"(b));
}
__device__ __forceinline__ void add2(uint64_t& d, uint64_t a) {
    asm("add.rn.f32x2 %0, %0, %1;" : "+l"(d) : "l"(a));
}

// m16n8k16 fp16 MMA, fp32 accumulate
__device__ __forceinline__ void mma_f16(float d[4],
    uint32_t a0, uint32_t a1, uint32_t a2, uint32_t a3,
    uint32_t b0, uint32_t b1)
{
    asm volatile(
        "mma.sync.aligned.m16n8k16.row.col.f32.f16.f16.f32 "
        "{%0,%1,%2,%3}, {%4,%5,%6,%7}, {%8,%9}, {%0,%1,%2,%3};"
        : "+f"(d[0]), "+f"(d[1]), "+f"(d[2]), "+f"(d[3])
        : "r"(a0), "r"(a1), "r"(a2), "r"(a3), "r"(b0), "r"(b1));
}

// smem layout (32-bit words)
static constexpr int SW_W4   = 0;                       // [64 o][WHW] fp16 [o][k]
static constexpr int SW_V0   = 64 * WHW;                // [128 p][VHW] fp16 buf 0
static constexpr int SW_V1   = SW_V0 + PTS * VHW;       // buf 1
static constexpr int SW_BIAS = SW_V1 + PTS * VHW;       // [64] f32
static constexpr int SMEM_WORDS = SW_BIAS + 64;
static constexpr int SMEM_BYTES = SMEM_WORDS * 4;       // ~169.5 KB

// ---------------------------------------------------------------------------
// Prep 0: positions -> float4 rows (tiny, feeds prep_rest's dp blocks)
// ---------------------------------------------------------------------------
__global__ void __launch_bounds__(256) prep_pos(const float* __restrict__ pos) {
    const int t = blockIdx.x * blockDim.x + threadIdx.x;   // over B*N
    const int b = t / NN;
    const int n = t - b * NN;
    const float* p = pos + (size_t)b * 3 * NN;
    g_posT[t] = make_float4(p[n], p[NN + n], p[2 * NN + n], 0.f);
}

// ---------------------------------------------------------------------------
// Prep 1: blocks [0, 2048) transpose features (fp16 out);
// blocks [2048, 6144) pack dp pairs {fp16 dx,dy,dz x2 + idx x2} (overlapped).
// ---------------------------------------------------------------------------
__global__ void __launch_bounds__(256) prep_rest(
    const float4* __restrict__ f4,
    const int*    __restrict__ nb)
{
    __shared__ float tile[64][65];
    const int bx = blockIdx.x;
    if (bx < (NN / 64) * BB) {
        const int b  = bx >> 9;
        const int n0 = (bx & 511) * 64;
        const int tx = threadIdx.x & 15;
        const int ty = threadIdx.x >> 4;
        const float4* src = f4 + (size_t)b * CINC * (NN / 4) + (n0 >> 2);
        #pragma unroll
        for (int cc = ty; cc < 64; cc += 16) {
            float4 v = __ldg(&src[(size_t)cc * (NN / 4) + tx]);
            tile[4 * tx + 0][cc] = v.x;
            tile[4 * tx + 1][cc] = v.y;
            tile[4 * tx + 2][cc] = v.z;
            tile[4 * tx + 3][cc] = v.w;
        }
        __syncthreads();
        uint2* dst = (uint2*)(g_featH + ((size_t)b * NN + n0) * CINC);
        #pragma unroll
        for (int rr = ty; rr < 64; rr += 16) {
            __half2 h0 = __floats2half2_rn(tile[rr][4 * tx + 0], tile[rr][4 * tx + 1]);
            __half2 h1 = __floats2half2_rn(tile[rr][4 * tx + 2], tile[rr][4 * tx + 3]);
            uint2 u;
            u.x = *(uint32_t*)&h0;
            u.y = *(uint32_t*)&h1;
            dst[(size_t)rr * 16 + tx] = u;
        }
    } else {
        // dp pack: t over [b][n][kpair], kpair fastest -> coalesced writes
        const int t  = (bx - (NN / 64) * BB) * 256 + threadIdx.x;
        const int kp = t & 7;
        const int n  = (t >> 3) & (NN - 1);
        const int b  = t >> 18;
        const int k0 = 2 * kp;
        const int idx0 = __ldg(&nb[((size_t)b * KNB + k0) * NN + n]);
        const int idx1 = __ldg(&nb[((size_t)b * KNB + k0 + 1) * NN + n]);
        const float4 pg0 = __ldg(&g_posT[b * NN + idx0]);
        const float4 pg1 = __ldg(&g_posT[b * NN + idx1]);
        const float4 ps  = __ldg(&g_posT[b * NN + n]);
        __half2 hxy0 = __floats2half2_rn(pg0.x - ps.x, pg0.y - ps.y);
        __half2 hzx1 = __floats2half2_rn(pg0.z - ps.z, pg1.x - ps.x);
        __half2 hyz1 = __floats2half2_rn(pg1.y - ps.y, pg1.z - ps.z);
        uint4 q;
        q.x = *(uint32_t*)&hxy0;
        q.y = *(uint32_t*)&hzx1;
        q.z = *(uint32_t*)&hyz1;
        q.w = (uint32_t)idx0 | ((uint32_t)idx1 << 16);
        g_dp2[t] = q;
    }
}

// ---------------------------------------------------------------------------
// Gather+reduce one 128-pt tile into Vbuf (all 32 warps; 4 points each).
// Per k-pair: one uniform LDG.128 (packed dp) + two coalesced feat LDGs.
// ---------------------------------------------------------------------------
__device__ __forceinline__ void gather_tile(
    __half* __restrict__ Vbuf, int tile, int w, int l,
    const __half2* __restrict__ featH2)
{
    const int b  = tile >> 8;                 // NN/PTS = 256 tiles/batch
    const int n0 = (tile & 255) * PTS;
    const int bbase = b * NN;                 // feat row base (half2-rows/32)

    #pragma unroll 1
    for (int i = 0; i < 4; i++) {             // 32 warps x 4 points
        const int p = w * 4 + i;
        const uint4* dpRow = g_dp2 + ((size_t)bbase + n0 + p) * 8;
        uint64_t a0 = 0ull, a1 = 0ull, a2 = 0ull, af = 0ull;
        #pragma unroll
        for (int kp = 0; kp < 8; kp++) {
            uint4 q = __ldg(&dpRow[kp]);                  // uniform: 1 wf
            float2 d01 = __half22float2(*(__half2*)&q.x); // dx0, dy0
            float2 d23 = __half22float2(*(__half2*)&q.y); // dz0, dx1
            float2 d45 = __half22float2(*(__half2*)&q.z); // dy1, dz1
            int idx0 = q.w & 0xFFFF;
            int idx1 = q.w >> 16;
            __half2 fh0 = __ldg(&featH2[((size_t)(bbase + idx0) << 5) + l]);
            __half2 fh1 = __ldg(&featH2[((size_t)(bbase + idx1) << 5) + l]);
            float2 f0 = __half22float2(fh0);
            float2 f1 = __half22float2(fh1);
            uint64_t fp0 = pack2(f0.x, f0.y);
            uint64_t fp1 = pack2(f1.x, f1.y);
            fma2(a0, pack2(d01.x, d01.x), fp0);
            fma2(a1, pack2(d01.y, d01.y), fp0);
            fma2(a2, pack2(d23.x, d23.x), fp0);
            add2(af, fp0);
            fma2(a0, pack2(d23.y, d23.y), fp1);
            fma2(a1, pack2(d45.x, d45.x), fp1);
            fma2(a2, pack2(d45.y, d45.y), fp1);
            add2(af, fp1);
        }

        // V row p (fp16): cc = d*64 + 2l as one half2 store
        __half* vrow = Vbuf + p * (2 * VHW);
        float x, y;
        unpack2(x, y, a0);
        *(__half2*)&vrow[0 * 64 + 2 * l] = __floats2half2_rn(x, y);
        unpack2(x, y, a1);
        *(__half2*)&vrow[1 * 64 + 2 * l] = __floats2half2_rn(x, y);
        unpack2(x, y, a2);
        *(__half2*)&vrow[2 * 64 + 2 * l] = __floats2half2_rn(x, y);
        unpack2(x, y, af);
        *(__half2*)&vrow[3 * 64 + 2 * l] = __floats2half2_rn(x, y);
    }
}

// ---------------------------------------------------------------------------
// Persistent main: double-buffered V; per iteration every warp gathers tile
// t+GRIDM into V[par^1], warps 0-15 additionally GEMM tile t from V[par].
// ---------------------------------------------------------------------------
__global__ void __launch_bounds__(THREADS, 1) flexconv_main(
    const float* __restrict__ wt,    // [3][CIN][COUT]
    const float* __restrict__ wb,    // [CIN][COUT]
    const float* __restrict__ bias,  // [COUT]
    float* __restrict__ out)         // [B][COUT][N]
{
    extern __shared__ uint32_t smw[];
    uint32_t* W4w = smw + SW_W4;                 // word view of W4 [o][k]
    __half*   W4h = (__half*)W4w;
    uint32_t* Vw[2] = { smw + SW_V0, smw + SW_V1 };
    float*    bs  = (float*)(smw + SW_BIAS);

    const int tid = threadIdx.x;
    const int w   = tid >> 5, l = tid & 31;

    if (tid < COUTC) bs[tid] = bias[tid];

    // stage W4 -> [o][k] fp16 once (gmem-coalesced over o)
    #pragma unroll
    for (int it = 0; it < (256 * 64) / THREADS; it++) {
        int t = tid + it * THREADS;
        int k = t >> 6, o = t & 63;
        float v = (k < 192) ? wt[t] : wb[t - 192 * 64];
        W4h[o * (2 * WHW) + k] = __float2half_rn(v);
    }

    const __half2* featH2 = (const __half2*)g_featH;
    // GEMM warp tile (warps 0-15): m16 x n32
    const int mw = w & 7;            // M tile (8 x 16 rows)
    const int nh = w >> 3;           // N half (2 x 32 cols); valid for w<16
    const int r  = l >> 2, c = l & 3;

    // prologue: fill buf 0 with this CTA's first tile
    gather_tile((__half*)Vw[0], blockIdx.x, w, l, featH2);
    __syncthreads();   // also publishes W4 + bias

    int par = 0;
    for (int tile = blockIdx.x; tile < NTILES; tile += GRIDM) {
        // ------- all warps: gather NEXT tile into the other buffer --------
        const int t2 = tile + GRIDM;
        if (t2 < NTILES)
            gather_tile((__half*)Vw[par ^ 1], t2, w, l, featH2);

        // ------- warps 0-15: fp16 GEMM 128x64x256 on current buffer ------
        if (w < 16) {
            const int b  = tile >> 8;
            const int n0 = (tile & 255) * PTS;

            float acc[4][4];
            #pragma unroll
            for (int t = 0; t < 4; t++)
                acc[t][0] = acc[t][1] = acc[t][2] = acc[t][3] = 0.f;

            const uint32_t* Va = Vw[par] + (16 * mw + r) * VHW + c;   // words
            const uint32_t* Wb = W4w + (32 * nh + r) * WHW + c;       // [o][k]

            #pragma unroll 8
            for (int kw = 0; kw < 128; kw += 8) {   // k in words (k16/step)
                uint32_t a0 = Va[kw];
                uint32_t a1 = Va[8 * VHW + kw];
                uint32_t a2 = Va[kw + 4];
                uint32_t a3 = Va[8 * VHW + kw + 4];
                #pragma unroll
                for (int t = 0; t < 4; t++) {
                    uint32_t b0 = Wb[8 * t * WHW + kw];
                    uint32_t b1 = Wb[8 * t * WHW + kw + 4];
                    mma_f16(acc[t], a0, a1, a2, a3, b0, b1);
                }
            }

            float* op = out + (size_t)b * COUTC * NN + n0 + 16 * mw + r;
            #pragma unroll
            for (int t = 0; t < 4; t++) {
                int o0 = 32 * nh + 8 * t + 2 * c;
                float bv0 = bs[o0], bv1 = bs[o0 + 1];
                op[(size_t)o0 * NN]           = acc[t][0] + bv0;
                op[(size_t)(o0 + 1) * NN]     = acc[t][1] + bv1;
                op[(size_t)o0 * NN + 8]       = acc[t][2] + bv0;
                op[(size_t)(o0 + 1) * NN + 8] = acc[t][3] + bv1;
            }
        }
        __syncthreads();   // gather writes to V[par^1] done; V[par] reads done
        par ^= 1;
    }
}

// ---------------------------------------------------------------------------
extern "C" void kernel_launch(void* const* d_in, const int* in_sizes, int n_in,
                              void* d_out, int out_size) {
    const float* feat = (const float*)d_in[0];   // [B][CIN][N]
    const float* wt   = (const float*)d_in[1];   // [3][CIN][COUT]
    const float* wb   = (const float*)d_in[2];   // [CIN][COUT]
    const float* bias = (const float*)d_in[3];   // [COUT]
    const int*   nb   = (const int*)  d_in[4];   // [B][K][N]
    const float* pos  = (const float*)d_in[5];   // [B][3][N]
    float* out = (float*)d_out;

    prep_pos<<<(BB * NN) / 256, 256>>>(pos);
    const int nrest = (NN / 64) * BB + (BB * NN * 8) / 256;   // 2048 + 4096
    prep_rest<<<nrest, 256>>>((const float4*)feat, nb);

    cudaFuncSetAttribute(flexconv_main,
                         cudaFuncAttributeMaxDynamicSharedMemorySize, SMEM_BYTES);
    flexconv_main<<<GRIDM, THREADS, SMEM_BYTES>>>(wt, wb, bias, out);
}